// round 1
// baseline (speedup 1.0000x reference)
#include <cuda_runtime.h>
#include <math.h>

#define SEQ 1024
#define HID 4096
#define NH  64
#define HD  64

// Scratch (allocation-free rule: __device__ globals)
__device__ float g_kb[SEQ * HID];
__device__ float g_vb[SEQ * HID];
__device__ float g_rb[SEQ * HID];
__device__ float g_gb[SEQ * HID];
__device__ float g_ab[SEQ * HID];

#define BM 128
#define BN 128
#define BK 8

// ---------------------------------------------------------------------------
// Projection GEMM: out[m,n] = sum_k mix(hidden)[m,k] * W[n,k]
// mix fused into A-tile load; SiLU fused into gate epilogue.
// blockIdx.z selects projection {key, value, receptance, gate}.
// ---------------------------------------------------------------------------
__global__ __launch_bounds__(256) void proj_kernel(
    const float* __restrict__ hidden,
    const float* __restrict__ wk, const float* __restrict__ wv,
    const float* __restrict__ wr, const float* __restrict__ wg,
    const float* __restrict__ mk, const float* __restrict__ mv,
    const float* __restrict__ mr, const float* __restrict__ mg)
{
    const float* W;
    const float* mixv;
    float* out;
    bool do_silu = false;
    switch (blockIdx.z) {
        case 0:  W = wk; mixv = mk; out = g_kb; break;
        case 1:  W = wv; mixv = mv; out = g_vb; break;
        case 2:  W = wr; mixv = mr; out = g_rb; break;
        default: W = wg; mixv = mg; out = g_gb; do_silu = true; break;
    }

    __shared__ float As[BK][BM];
    __shared__ float Bs[BK][BN];

    const int tid = threadIdx.x;
    const int tx = tid & 15;
    const int ty = tid >> 4;
    const int m0 = blockIdx.y * BM;
    const int n0 = blockIdx.x * BN;
    const int lrow = tid >> 1;          // 0..127
    const int lcol = (tid & 1) * 4;     // 0 or 4

    float acc[8][8];
    #pragma unroll
    for (int i = 0; i < 8; i++)
        #pragma unroll
        for (int j = 0; j < 8; j++)
            acc[i][j] = 0.f;

    const int m = m0 + lrow;
    const float* hrow = hidden + (size_t)m * HID;
    const float* srow = hidden + (size_t)(m - 1) * HID;   // only read if m>0
    const float* wrow = W + (size_t)(n0 + lrow) * HID;

    for (int k0 = 0; k0 < HID; k0 += BK) {
        float4 hv = *(const float4*)(hrow + k0 + lcol);
        float4 sv = make_float4(0.f, 0.f, 0.f, 0.f);
        if (m > 0) sv = *(const float4*)(srow + k0 + lcol);
        float4 mvx = *(const float4*)(mixv + k0 + lcol);
        As[lcol + 0][lrow] = hv.x * mvx.x + sv.x * (1.f - mvx.x);
        As[lcol + 1][lrow] = hv.y * mvx.y + sv.y * (1.f - mvx.y);
        As[lcol + 2][lrow] = hv.z * mvx.z + sv.z * (1.f - mvx.z);
        As[lcol + 3][lrow] = hv.w * mvx.w + sv.w * (1.f - mvx.w);

        float4 bv = *(const float4*)(wrow + k0 + lcol);
        Bs[lcol + 0][lrow] = bv.x;
        Bs[lcol + 1][lrow] = bv.y;
        Bs[lcol + 2][lrow] = bv.z;
        Bs[lcol + 3][lrow] = bv.w;
        __syncthreads();

        #pragma unroll
        for (int kk = 0; kk < BK; kk++) {
            float4 a0 = *(const float4*)&As[kk][ty * 8];
            float4 a1 = *(const float4*)&As[kk][ty * 8 + 4];
            float4 b0 = *(const float4*)&Bs[kk][tx * 8];
            float4 b1 = *(const float4*)&Bs[kk][tx * 8 + 4];
            float a[8] = {a0.x, a0.y, a0.z, a0.w, a1.x, a1.y, a1.z, a1.w};
            float b[8] = {b0.x, b0.y, b0.z, b0.w, b1.x, b1.y, b1.z, b1.w};
            #pragma unroll
            for (int i = 0; i < 8; i++)
                #pragma unroll
                for (int j = 0; j < 8; j++)
                    acc[i][j] = fmaf(a[i], b[j], acc[i][j]);
        }
        __syncthreads();
    }

    #pragma unroll
    for (int i = 0; i < 8; i++) {
        int mi = m0 + ty * 8 + i;
        #pragma unroll
        for (int j = 0; j < 8; j += 4) {
            float4 v = make_float4(acc[i][j], acc[i][j + 1], acc[i][j + 2], acc[i][j + 3]);
            if (do_silu) {
                v.x = v.x / (1.f + expf(-v.x));
                v.y = v.y / (1.f + expf(-v.y));
                v.z = v.z / (1.f + expf(-v.z));
                v.w = v.w / (1.f + expf(-v.w));
            }
            *(float4*)(out + (size_t)mi * HID + n0 + tx * 8 + j) = v;
        }
    }
}

// ---------------------------------------------------------------------------
// WKV recurrence + fused GroupNorm + gate.
// One CTA per head. 256 threads: e = tid&63 (value column), dg = tid>>6
// (16 key-rows of state per thread).
//   o_e   = sum_d r_d * (tf_d * k_d * v_e + state[d][e])
//   state = k_d * v_e + td_d * state
// Then per (t,h): GroupNorm over the 64 o's, scale/shift, multiply by gate.
// ---------------------------------------------------------------------------
__global__ __launch_bounds__(256) void wkv_kernel(
    const float* __restrict__ time_decay, const float* __restrict__ time_faaaa,
    const float* __restrict__ gn_w, const float* __restrict__ gn_b)
{
    const int h = blockIdx.x;
    const int tid = threadIdx.x;
    const int e = tid & 63;
    const int dg = tid >> 6;       // 0..3
    const int dbase = dg * 16;

    __shared__ float ks[64], rs[64], vs[64], gs[64];
    __shared__ float opart[4][64];
    __shared__ float red[4];

    float td[16], tf[16], st[16];
    #pragma unroll
    for (int j = 0; j < 16; j++) {
        int d = dbase + j;
        td[j] = expf(-expf(time_decay[h * HD + d]));
        tf[j] = time_faaaa[h * HD + d];
        st[j] = 0.f;
    }
    const float gw = gn_w[h * HD + e];
    const float gb = gn_b[h * HD + e];

    const float* kb = g_kb + h * HD;
    const float* rb = g_rb + h * HD;
    const float* vb = g_vb + h * HD;
    const float* gp = g_gb + h * HD;

    for (int t = 0; t < SEQ; t++) {
        const int base = t * HID;
        if (tid < 64)        ks[tid]       = kb[base + tid];
        else if (tid < 128)  rs[tid - 64]  = rb[base + tid - 64];
        else if (tid < 192)  vs[tid - 128] = vb[base + tid - 128];
        else                 gs[tid - 192] = gp[base + tid - 192];
        __syncthreads();

        const float gval = gs[e];   // capture before shared reuse hazard
        const float ve = vs[e];
        float o0 = 0.f, o1 = 0.f;
        #pragma unroll
        for (int j = 0; j < 16; j += 2) {
            float kv0 = ks[dbase + j] * ve;
            o0 = fmaf(rs[dbase + j], fmaf(tf[j], kv0, st[j]), o0);
            st[j] = fmaf(td[j], st[j], kv0);
            float kv1 = ks[dbase + j + 1] * ve;
            o1 = fmaf(rs[dbase + j + 1], fmaf(tf[j + 1], kv1, st[j + 1]), o1);
            st[j + 1] = fmaf(td[j + 1], st[j + 1], kv1);
        }
        opart[dg][e] = o0 + o1;
        __syncthreads();

        float o = 0.f;
        if (tid < 64) {
            o = opart[0][e] + opart[1][e] + opart[2][e] + opart[3][e];
            float s = o, s2 = o * o;
            #pragma unroll
            for (int off = 16; off > 0; off >>= 1) {
                s  += __shfl_xor_sync(0xffffffffu, s,  off);
                s2 += __shfl_xor_sync(0xffffffffu, s2, off);
            }
            if ((tid & 31) == 0) {
                red[(tid >> 5) * 2]     = s;
                red[(tid >> 5) * 2 + 1] = s2;
            }
        }
        __syncthreads();

        if (tid < 64) {
            float mean = (red[0] + red[2]) * (1.f / 64.f);
            float m2   = (red[1] + red[3]) * (1.f / 64.f);
            float var = m2 - mean * mean;
            float xn = (o - mean) * rsqrtf(var + 1e-5f) * gw + gb;
            g_ab[base + h * HD + e] = xn * gval;
        }
        // No extra barrier needed: next-iter shared writes are ordered by
        // the 3 barriers above (gval captured early).
    }
}

// ---------------------------------------------------------------------------
// Output GEMM: out[m,n] = sum_k g_ab[m,k] * Wout[n,k]
// ---------------------------------------------------------------------------
__global__ __launch_bounds__(256) void out_kernel(
    const float* __restrict__ W, float* __restrict__ outp)
{
    __shared__ float As[BK][BM];
    __shared__ float Bs[BK][BN];

    const int tid = threadIdx.x;
    const int tx = tid & 15;
    const int ty = tid >> 4;
    const int m0 = blockIdx.y * BM;
    const int n0 = blockIdx.x * BN;
    const int lrow = tid >> 1;
    const int lcol = (tid & 1) * 4;

    float acc[8][8];
    #pragma unroll
    for (int i = 0; i < 8; i++)
        #pragma unroll
        for (int j = 0; j < 8; j++)
            acc[i][j] = 0.f;

    const float* arow = g_ab + (size_t)(m0 + lrow) * HID;
    const float* wrow = W + (size_t)(n0 + lrow) * HID;

    for (int k0 = 0; k0 < HID; k0 += BK) {
        float4 av = *(const float4*)(arow + k0 + lcol);
        As[lcol + 0][lrow] = av.x;
        As[lcol + 1][lrow] = av.y;
        As[lcol + 2][lrow] = av.z;
        As[lcol + 3][lrow] = av.w;
        float4 bv = *(const float4*)(wrow + k0 + lcol);
        Bs[lcol + 0][lrow] = bv.x;
        Bs[lcol + 1][lrow] = bv.y;
        Bs[lcol + 2][lrow] = bv.z;
        Bs[lcol + 3][lrow] = bv.w;
        __syncthreads();

        #pragma unroll
        for (int kk = 0; kk < BK; kk++) {
            float4 a0 = *(const float4*)&As[kk][ty * 8];
            float4 a1 = *(const float4*)&As[kk][ty * 8 + 4];
            float4 b0 = *(const float4*)&Bs[kk][tx * 8];
            float4 b1 = *(const float4*)&Bs[kk][tx * 8 + 4];
            float a[8] = {a0.x, a0.y, a0.z, a0.w, a1.x, a1.y, a1.z, a1.w};
            float b[8] = {b0.x, b0.y, b0.z, b0.w, b1.x, b1.y, b1.z, b1.w};
            #pragma unroll
            for (int i = 0; i < 8; i++)
                #pragma unroll
                for (int j = 0; j < 8; j++)
                    acc[i][j] = fmaf(a[i], b[j], acc[i][j]);
        }
        __syncthreads();
    }

    #pragma unroll
    for (int i = 0; i < 8; i++) {
        int mi = m0 + ty * 8 + i;
        #pragma unroll
        for (int j = 0; j < 8; j += 4) {
            float4 v = make_float4(acc[i][j], acc[i][j + 1], acc[i][j + 2], acc[i][j + 3]);
            *(float4*)(outp + (size_t)mi * HID + n0 + tx * 8 + j) = v;
        }
    }
}

// ---------------------------------------------------------------------------
extern "C" void kernel_launch(void* const* d_in, const int* in_sizes, int n_in,
                              void* d_out, int out_size)
{
    const float* hidden     = (const float*)d_in[0];
    const float* w_key      = (const float*)d_in[1];
    const float* w_value    = (const float*)d_in[2];
    const float* w_recept   = (const float*)d_in[3];
    const float* w_gate     = (const float*)d_in[4];
    const float* w_output   = (const float*)d_in[5];
    const float* tm_key     = (const float*)d_in[6];
    const float* tm_value   = (const float*)d_in[7];
    const float* tm_recept  = (const float*)d_in[8];
    const float* tm_gate    = (const float*)d_in[9];
    const float* time_decay = (const float*)d_in[10];
    const float* time_faaaa = (const float*)d_in[11];
    const float* gn_w       = (const float*)d_in[12];
    const float* gn_b       = (const float*)d_in[13];

    dim3 gproj(HID / BN, SEQ / BM, 4);
    proj_kernel<<<gproj, 256>>>(hidden, w_key, w_value, w_recept, w_gate,
                                tm_key, tm_value, tm_recept, tm_gate);

    wkv_kernel<<<NH, 256>>>(time_decay, time_faaaa, gn_w, gn_b);

    dim3 gout(HID / BN, SEQ / BM, 1);
    out_kernel<<<gout, 256>>>(w_output, (float*)d_out);
}